// round 1
// baseline (speedup 1.0000x reference)
#include <cuda_runtime.h>
#include <math.h>

#define NL 6
#define NH 16
#define E  1024
#define V  50257
#define B  4
#define T  1024
#define BT (B*T)
#define HD 64

// ---------------- scratch (static device allocations; no cudaMalloc) --------
__device__ float g_x[BT * E];          // residual stream
__device__ float g_h[BT * E];          // layernorm output
__device__ float g_qkv[BT * 3 * E];    // qkv projection
__device__ float g_y[BT * E];          // attention output
__device__ float g_mlp[BT * 4 * E];    // MLP hidden
__device__ float g_nll[BT];            // per-row NLL

// ---------------- embedding -------------------------------------------------
__global__ void embed_kernel(const int* __restrict__ idx,
                             const float* __restrict__ wte,
                             const float* __restrict__ wpe,
                             float* __restrict__ out)
{
    int row = blockIdx.x;           // 0..BT-1
    int t = row % T;
    int tok = idx[row];
    const float* we = wte + (size_t)tok * E;
    const float* wp = wpe + (size_t)t * E;
    float* o = out + (size_t)row * E;
    for (int i = threadIdx.x; i < E; i += blockDim.x)
        o[i] = we[i] + wp[i];
}

// ---------------- layernorm -------------------------------------------------
__global__ void ln_kernel(const float* __restrict__ x,
                          const float* __restrict__ w,
                          const float* __restrict__ b,
                          float* __restrict__ out)
{
    int row = blockIdx.x;
    int tid = threadIdx.x;
    const float* xr = x + (size_t)row * E;
    float s = 0.f, ss = 0.f;
    for (int i = tid; i < E; i += blockDim.x) {
        float v = xr[i];
        s += v; ss += v * v;
    }
    __shared__ float rs[32], rss[32];
    #pragma unroll
    for (int o = 16; o > 0; o >>= 1) {
        s  += __shfl_xor_sync(0xffffffffu, s, o);
        ss += __shfl_xor_sync(0xffffffffu, ss, o);
    }
    int wid = tid >> 5, lid = tid & 31;
    if (lid == 0) { rs[wid] = s; rss[wid] = ss; }
    __syncthreads();
    if (tid < 32) {
        int nw = blockDim.x >> 5;
        float a = (tid < nw) ? rs[tid] : 0.f;
        float c = (tid < nw) ? rss[tid] : 0.f;
        #pragma unroll
        for (int o = 16; o > 0; o >>= 1) {
            a += __shfl_xor_sync(0xffffffffu, a, o);
            c += __shfl_xor_sync(0xffffffffu, c, o);
        }
        if (tid == 0) { rs[0] = a; rss[0] = c; }
    }
    __syncthreads();
    float mu  = rs[0] * (1.0f / E);
    float var = rss[0] * (1.0f / E) - mu * mu;
    float r = rsqrtf(var + 1e-5f);
    float* orow = out + (size_t)row * E;
    for (int i = tid; i < E; i += blockDim.x)
        orow[i] = (xr[i] - mu) * r * w[i] + b[i];
}

// ---------------- SGEMM: C[M,N] = A[M,K] * Bw[N,K]^T (+Res, optional GELU) --
#define BM 128
#define BN 128
#define BKD 8

__global__ void __launch_bounds__(256)
sgemm_nt(const float* __restrict__ A, const float* __restrict__ Bw,
         float* __restrict__ C, const float* __restrict__ Res,
         int M, int N, int K, int act_gelu)
{
    __shared__ float As[BKD][BM];
    __shared__ float Bs[BKD][BN];
    int tid = threadIdx.x;
    int tx = tid & 15, ty = tid >> 4;
    int row0 = blockIdx.y * BM, col0 = blockIdx.x * BN;

    float acc[8][8];
    #pragma unroll
    for (int i = 0; i < 8; i++)
        #pragma unroll
        for (int j = 0; j < 8; j++) acc[i][j] = 0.f;

    int lr = tid >> 1;            // 0..127
    int lk = (tid & 1) * 4;       // 0 or 4
    const float* Aptr = A  + (size_t)(row0 + lr) * K + lk;
    const float* Bptr = Bw + (size_t)(col0 + lr) * K + lk;
    bool aok = (row0 + lr) < M;
    bool bok = (col0 + lr) < N;

    for (int k0 = 0; k0 < K; k0 += BKD) {
        float4 av = make_float4(0.f, 0.f, 0.f, 0.f);
        float4 bv = make_float4(0.f, 0.f, 0.f, 0.f);
        if (aok) av = *(const float4*)(Aptr + k0);
        if (bok) bv = *(const float4*)(Bptr + k0);
        As[lk + 0][lr] = av.x; As[lk + 1][lr] = av.y;
        As[lk + 2][lr] = av.z; As[lk + 3][lr] = av.w;
        Bs[lk + 0][lr] = bv.x; Bs[lk + 1][lr] = bv.y;
        Bs[lk + 2][lr] = bv.z; Bs[lk + 3][lr] = bv.w;
        __syncthreads();
        #pragma unroll
        for (int kk = 0; kk < BKD; kk++) {
            float a[8], bb[8];
            #pragma unroll
            for (int i = 0; i < 4; i++) {
                a[i]      = As[kk][ty * 4 + i];
                a[4 + i]  = As[kk][64 + ty * 4 + i];
                bb[i]     = Bs[kk][tx * 4 + i];
                bb[4 + i] = Bs[kk][64 + tx * 4 + i];
            }
            #pragma unroll
            for (int i = 0; i < 8; i++)
                #pragma unroll
                for (int j = 0; j < 8; j++)
                    acc[i][j] += a[i] * bb[j];
        }
        __syncthreads();
    }

    #pragma unroll
    for (int i = 0; i < 8; i++) {
        int mrow = row0 + ((i < 4) ? (ty * 4 + i) : (64 + ty * 4 + (i - 4)));
        if (mrow >= M) continue;
        #pragma unroll
        for (int j = 0; j < 8; j++) {
            int ncol = col0 + ((j < 4) ? (tx * 4 + j) : (64 + tx * 4 + (j - 4)));
            if (ncol >= N) continue;
            size_t off = (size_t)mrow * N + ncol;
            float v = acc[i][j];
            if (Res) v += Res[off];
            if (act_gelu) v = 0.5f * v * (1.0f + erff(v * 0.70710678118654752f));
            C[off] = v;
        }
    }
}

// ---------------- flash attention (fp32, causal, hd=64) ---------------------
#define QT 128
#define KT 64
#define KCH 16

__global__ void __launch_bounds__(128)
attn_kernel(const float* __restrict__ qkv, float* __restrict__ y)
{
    int qt = blockIdx.x, h = blockIdx.y, b = blockIdx.z;
    int tid = threadIdx.x;
    int qg = qt * QT + tid;             // this thread's query index
    __shared__ float Ks[KT][HD];
    __shared__ float Vs[KT][HD];

    float q[HD], o[HD];
    const float* qp = qkv + ((size_t)(b * T + qg) * 3 * E) + h * HD;
    const float scale = 0.125f;         // 1/sqrt(64)
    #pragma unroll
    for (int d = 0; d < HD; d += 4) {
        float4 v = *(const float4*)(qp + d);
        q[d] = v.x * scale; q[d+1] = v.y * scale;
        q[d+2] = v.z * scale; q[d+3] = v.w * scale;
        o[d] = 0.f; o[d+1] = 0.f; o[d+2] = 0.f; o[d+3] = 0.f;
    }
    float m = -INFINITY, l = 0.f;
    int kend = qt * QT + QT;            // block-uniform

    for (int k0 = 0; k0 < kend; k0 += KT) {
        __syncthreads();
        // cooperative K/V tile load: 64 rows x 64 floats each
        for (int i = tid; i < KT * HD / 4; i += 128) {
            int j = i >> 4;             // key row within tile
            int c = (i & 15) << 2;      // dim offset
            const float* kp = qkv + ((size_t)(b * T + k0 + j) * 3 * E) + E + h * HD + c;
            *(float4*)&Ks[j][c] = *(const float4*)kp;
            *(float4*)&Vs[j][c] = *(const float4*)(kp + E);
        }
        __syncthreads();

        #pragma unroll 1
        for (int jc = 0; jc < KT; jc += KCH) {
            if (k0 + jc > qg) break;    // entire chunk masked (no syncs inside)
            float s[KCH];
            float cm = -INFINITY;
            #pragma unroll
            for (int jj = 0; jj < KCH; jj++) {
                int kg = k0 + jc + jj;
                float acc = 0.f;
                #pragma unroll
                for (int d = 0; d < HD; d++) acc += q[d] * Ks[jc + jj][d];
                s[jj] = (kg <= qg) ? acc : -INFINITY;
                cm = fmaxf(cm, s[jj]);
            }
            float nm = fmaxf(m, cm);
            float corr = __expf(m - nm);
            l *= corr;
            #pragma unroll
            for (int d = 0; d < HD; d++) o[d] *= corr;
            #pragma unroll
            for (int jj = 0; jj < KCH; jj++) {
                float p = __expf(s[jj] - nm);
                l += p;
                #pragma unroll
                for (int d = 0; d < HD; d++) o[d] += p * Vs[jc + jj][d];
            }
            m = nm;
        }
    }
    float inv = 1.f / l;
    float* yp = y + ((size_t)(b * T + qg) * E) + h * HD;
    #pragma unroll
    for (int d = 0; d < HD; d += 4) {
        float4 v = make_float4(o[d] * inv, o[d+1] * inv, o[d+2] * inv, o[d+3] * inv);
        *(float4*)(yp + d) = v;
    }
}

// ---------------- loss ------------------------------------------------------
__global__ void loss_rows_kernel(const float* __restrict__ logits,
                                 const int* __restrict__ tgt)
{
    int row = blockIdx.x;
    int tid = threadIdx.x;
    const float* lr = logits + (size_t)row * V;
    __shared__ float red[32];

    float mx = -INFINITY;
    for (int i = tid; i < V; i += 256) mx = fmaxf(mx, lr[i]);
    #pragma unroll
    for (int o = 16; o > 0; o >>= 1)
        mx = fmaxf(mx, __shfl_xor_sync(0xffffffffu, mx, o));
    if ((tid & 31) == 0) red[tid >> 5] = mx;
    __syncthreads();
    if (tid < 32) {
        float v = (tid < 8) ? red[tid] : -INFINITY;
        #pragma unroll
        for (int o = 16; o > 0; o >>= 1)
            v = fmaxf(v, __shfl_xor_sync(0xffffffffu, v, o));
        if (tid == 0) red[0] = v;
    }
    __syncthreads();
    mx = red[0];
    __syncthreads();

    float sum = 0.f;
    for (int i = tid; i < V; i += 256) sum += __expf(lr[i] - mx);
    #pragma unroll
    for (int o = 16; o > 0; o >>= 1)
        sum += __shfl_xor_sync(0xffffffffu, sum, o);
    if ((tid & 31) == 0) red[tid >> 5] = sum;
    __syncthreads();
    if (tid == 0) {
        float tot = 0.f;
        for (int w = 0; w < 8; w++) tot += red[w];
        float lse = mx + logf(tot);
        int tg = tgt[row];
        g_nll[row] = (tg != -1) ? (lse - lr[tg]) : 0.f;
    }
}

__global__ void loss_final_kernel(const int* __restrict__ tgt,
                                  float* __restrict__ out_loss)
{
    int tid = threadIdx.x;
    float s = 0.f;
    int c = 0;
    for (int i = tid; i < BT; i += blockDim.x) {
        s += g_nll[i];
        if (tgt[i] != -1) c++;
    }
    __shared__ float sf[32];
    __shared__ int si[32];
    #pragma unroll
    for (int o = 16; o > 0; o >>= 1) {
        s += __shfl_xor_sync(0xffffffffu, s, o);
        c += __shfl_xor_sync(0xffffffffu, c, o);
    }
    if ((tid & 31) == 0) { sf[tid >> 5] = s; si[tid >> 5] = c; }
    __syncthreads();
    if (tid == 0) {
        int nw = blockDim.x >> 5;
        float ts = 0.f; int tc = 0;
        for (int w = 0; w < nw; w++) { ts += sf[w]; tc += si[w]; }
        out_loss[0] = ts / fmaxf((float)tc, 1.f);
    }
}

// ---------------- launch ----------------------------------------------------
extern "C" void kernel_launch(void* const* d_in, const int* in_sizes, int n_in,
                              void* d_out, int out_size)
{
    const int*   idx         = (const int*)d_in[0];
    const int*   targets     = (const int*)d_in[1];
    const float* wte         = (const float*)d_in[2];
    const float* wpe         = (const float*)d_in[3];
    const float* ln1_w       = (const float*)d_in[4];
    const float* ln1_b       = (const float*)d_in[5];
    const float* attn_w      = (const float*)d_in[6];
    const float* attn_proj_w = (const float*)d_in[7];
    const float* ln2_w       = (const float*)d_in[8];
    const float* ln2_b       = (const float*)d_in[9];
    const float* fc_w        = (const float*)d_in[10];
    const float* fc_proj_w   = (const float*)d_in[11];
    const float* lnf_w       = (const float*)d_in[12];
    const float* lnf_b       = (const float*)d_in[13];
    const float* lm_w        = (const float*)d_in[14];
    float* out = (float*)d_out;

    float *gx, *gh, *gqkv, *gy, *gmlp;
    cudaGetSymbolAddress((void**)&gx,   g_x);
    cudaGetSymbolAddress((void**)&gh,   g_h);
    cudaGetSymbolAddress((void**)&gqkv, g_qkv);
    cudaGetSymbolAddress((void**)&gy,   g_y);
    cudaGetSymbolAddress((void**)&gmlp, g_mlp);

    embed_kernel<<<BT, 256>>>(idx, wte, wpe, gx);

    for (int i = 0; i < NL; i++) {
        // attention block
        ln_kernel<<<BT, 256>>>(gx, ln1_w + (size_t)i * E, ln1_b + (size_t)i * E, gh);
        sgemm_nt<<<dim3((3 * E) / BN, BT / BM), 256>>>(
            gh, attn_w + (size_t)i * 3 * E * E, gqkv, nullptr, BT, 3 * E, E, 0);
        attn_kernel<<<dim3(T / QT, NH, B), 128>>>(gqkv, gy);
        sgemm_nt<<<dim3(E / BN, BT / BM), 256>>>(
            gy, attn_proj_w + (size_t)i * E * E, gx, gx, BT, E, E, 0);
        // MLP block
        ln_kernel<<<BT, 256>>>(gx, ln2_w + (size_t)i * E, ln2_b + (size_t)i * E, gh);
        sgemm_nt<<<dim3((4 * E) / BN, BT / BM), 256>>>(
            gh, fc_w + (size_t)i * 4 * E * E, gmlp, nullptr, BT, 4 * E, E, 1);
        sgemm_nt<<<dim3(E / BN, BT / BM), 256>>>(
            gmlp, fc_proj_w + (size_t)i * E * 4 * E, gx, gx, BT, E, 4 * E, 0);
    }

    ln_kernel<<<BT, 256>>>(gx, lnf_w, lnf_b, gh);
    sgemm_nt<<<dim3((V + BN - 1) / BN, BT / BM), 256>>>(
        gh, lm_w, out, nullptr, BT, V, E, 0);

    long long btv = (long long)BT * V;
    if ((long long)out_size > btv) {
        loss_rows_kernel<<<BT, 256>>>(out, targets);
        loss_final_kernel<<<1, 1024>>>(targets, out + btv);
    }
}

// round 2
// speedup vs baseline: 1.6191x; 1.6191x over previous
#include <cuda_runtime.h>
#include <math.h>

#define NL 6
#define NH 16
#define E  1024
#define V  50257
#define B  4
#define T  1024
#define BT (B*T)
#define HD 64

// ---------------- scratch (static device allocations; no cudaMalloc) --------
__device__ float g_x[BT * E];          // residual stream
__device__ float g_h[BT * E];          // layernorm output
__device__ float g_qkv[BT * 3 * E];    // qkv projection
__device__ float g_y[BT * E];          // attention output
__device__ float g_mlp[BT * 4 * E];    // MLP hidden
__device__ float g_nll[BT];            // per-row NLL

// ---------------- embedding -------------------------------------------------
__global__ void embed_kernel(const int* __restrict__ idx,
                             const float* __restrict__ wte,
                             const float* __restrict__ wpe,
                             float* __restrict__ out)
{
    int row = blockIdx.x;
    int t = row % T;
    int tok = idx[row];
    const float* we = wte + (size_t)tok * E;
    const float* wp = wpe + (size_t)t * E;
    float* o = out + (size_t)row * E;
    for (int i = threadIdx.x; i < E; i += blockDim.x)
        o[i] = we[i] + wp[i];
}

// ---------------- layernorm -------------------------------------------------
__global__ void ln_kernel(const float* __restrict__ x,
                          const float* __restrict__ w,
                          const float* __restrict__ b,
                          float* __restrict__ out)
{
    int row = blockIdx.x;
    int tid = threadIdx.x;
    const float* xr = x + (size_t)row * E;
    float s = 0.f, ss = 0.f;
    for (int i = tid; i < E; i += blockDim.x) {
        float v = xr[i];
        s += v; ss += v * v;
    }
    __shared__ float rs[32], rss[32];
    #pragma unroll
    for (int o = 16; o > 0; o >>= 1) {
        s  += __shfl_xor_sync(0xffffffffu, s, o);
        ss += __shfl_xor_sync(0xffffffffu, ss, o);
    }
    int wid = tid >> 5, lid = tid & 31;
    if (lid == 0) { rs[wid] = s; rss[wid] = ss; }
    __syncthreads();
    if (tid < 32) {
        int nw = blockDim.x >> 5;
        float a = (tid < nw) ? rs[tid] : 0.f;
        float c = (tid < nw) ? rss[tid] : 0.f;
        #pragma unroll
        for (int o = 16; o > 0; o >>= 1) {
            a += __shfl_xor_sync(0xffffffffu, a, o);
            c += __shfl_xor_sync(0xffffffffu, c, o);
        }
        if (tid == 0) { rs[0] = a; rss[0] = c; }
    }
    __syncthreads();
    float mu  = rs[0] * (1.0f / E);
    float var = rss[0] * (1.0f / E) - mu * mu;
    float r = rsqrtf(var + 1e-5f);
    float* orow = out + (size_t)row * E;
    for (int i = tid; i < E; i += blockDim.x)
        orow[i] = (xr[i] - mu) * r * w[i] + b[i];
}

// ---------------- tf32 tensor-core GEMM -------------------------------------
// C[M,N] = A[M,K] @ W[N,K]^T (+Res, optional GELU), tf32 inputs, fp32 accum.
// BM=128, BN=128, BK=32, 256 threads (8 warps as 4x2), warp tile 32x64,
// mma.m16n8k8: per warp 2 m-tiles x 8 n-tiles.
#define BM 128
#define BN 128
#define BK 32
#define SST 36      // smem row stride (words): 4g+tg mod 32 -> conflict-free frags

__device__ __forceinline__ unsigned f2tf32(float f) {
    unsigned r;
    asm("cvt.rna.tf32.f32 %0, %1;" : "=r"(r) : "f"(f));
    return r;
}

__global__ void __launch_bounds__(256)
gemm_tf32(const float* __restrict__ A, const float* __restrict__ Bw,
          float* __restrict__ C, const float* __restrict__ Res,
          int M, int N, int K, int act_gelu)
{
    __shared__ float As[BM * SST];
    __shared__ float Bs[BN * SST];

    int tid = threadIdx.x;
    int warp = tid >> 5;
    int lane = tid & 31;
    int g  = lane >> 2;          // groupID 0..7
    int tg = lane & 3;           // thread-in-group 0..3
    int wm = warp & 3;           // warp row 0..3  (32 rows each)
    int wn = warp >> 2;          // warp col 0..1  (64 cols each)

    int row0 = blockIdx.y * BM;
    int col0 = blockIdx.x * BN;

    float acc[2][8][4];
    #pragma unroll
    for (int mi = 0; mi < 2; mi++)
        #pragma unroll
        for (int ni = 0; ni < 8; ni++)
            #pragma unroll
            for (int r = 0; r < 4; r++) acc[mi][ni][r] = 0.f;

    // g2s mapping: 1024 float4 per tile, 4 per thread
    int lrow[4], lf4[4];
    #pragma unroll
    for (int v = 0; v < 4; v++) {
        int lin = tid + v * 256;
        lrow[v] = lin >> 3;       // 0..127
        lf4[v]  = (lin & 7) * 4;  // k offset 0,4,...,28
    }

    for (int k0 = 0; k0 < K; k0 += BK) {
        #pragma unroll
        for (int v = 0; v < 4; v++) {
            int r = lrow[v], kc = lf4[v];
            // A tile (M edge assumed aligned: M=4096 always)
            float4 av = *(const float4*)(A + (size_t)(row0 + r) * K + k0 + kc);
            float* ap = As + r * SST + kc;
            ap[0] = __uint_as_float(f2tf32(av.x));
            ap[1] = __uint_as_float(f2tf32(av.y));
            ap[2] = __uint_as_float(f2tf32(av.z));
            ap[3] = __uint_as_float(f2tf32(av.w));
            // B tile (N edge guard for lm_head)
            float4 bv = make_float4(0.f, 0.f, 0.f, 0.f);
            if (col0 + r < N)
                bv = *(const float4*)(Bw + (size_t)(col0 + r) * K + k0 + kc);
            float* bp = Bs + r * SST + kc;
            bp[0] = __uint_as_float(f2tf32(bv.x));
            bp[1] = __uint_as_float(f2tf32(bv.y));
            bp[2] = __uint_as_float(f2tf32(bv.z));
            bp[3] = __uint_as_float(f2tf32(bv.w));
        }
        __syncthreads();

        #pragma unroll
        for (int kk = 0; kk < BK; kk += 8) {
            unsigned af[2][4];
            #pragma unroll
            for (int mi = 0; mi < 2; mi++) {
                const float* base = As + (wm * 32 + mi * 16 + g) * SST + kk + tg;
                af[mi][0] = __float_as_uint(base[0]);
                af[mi][1] = __float_as_uint(base[8 * SST]);
                af[mi][2] = __float_as_uint(base[4]);
                af[mi][3] = __float_as_uint(base[8 * SST + 4]);
            }
            unsigned bf[8][2];
            #pragma unroll
            for (int ni = 0; ni < 8; ni++) {
                const float* base = Bs + (wn * 64 + ni * 8 + g) * SST + kk + tg;
                bf[ni][0] = __float_as_uint(base[0]);
                bf[ni][1] = __float_as_uint(base[4]);
            }
            #pragma unroll
            for (int mi = 0; mi < 2; mi++)
                #pragma unroll
                for (int ni = 0; ni < 8; ni++) {
                    asm volatile(
                        "mma.sync.aligned.m16n8k8.row.col.f32.tf32.tf32.f32 "
                        "{%0,%1,%2,%3}, {%4,%5,%6,%7}, {%8,%9}, {%0,%1,%2,%3};\n"
                        : "+f"(acc[mi][ni][0]), "+f"(acc[mi][ni][1]),
                          "+f"(acc[mi][ni][2]), "+f"(acc[mi][ni][3])
                        : "r"(af[mi][0]), "r"(af[mi][1]), "r"(af[mi][2]), "r"(af[mi][3]),
                          "r"(bf[ni][0]), "r"(bf[ni][1]));
                }
        }
        __syncthreads();
    }

    // epilogue: c0={g,2tg} c1={g,2tg+1} c2={g+8,2tg} c3={g+8,2tg+1}
    #pragma unroll
    for (int mi = 0; mi < 2; mi++) {
        #pragma unroll
        for (int ni = 0; ni < 8; ni++) {
            int col = col0 + wn * 64 + ni * 8 + 2 * tg;
            #pragma unroll
            for (int half = 0; half < 2; half++) {
                int mrow = row0 + wm * 32 + mi * 16 + g + half * 8;
                #pragma unroll
                for (int c = 0; c < 2; c++) {
                    int ncol = col + c;
                    if (ncol >= N) continue;
                    size_t off = (size_t)mrow * N + ncol;
                    float v = acc[mi][ni][half * 2 + c];
                    if (Res) v += Res[off];
                    if (act_gelu) v = 0.5f * v * (1.0f + erff(v * 0.70710678118654752f));
                    C[off] = v;
                }
            }
        }
    }
}

// ---------------- flash attention (fp32, causal, hd=64) ---------------------
#define QT 128
#define KT 64
#define KCH 16

__global__ void __launch_bounds__(128)
attn_kernel(const float* __restrict__ qkv, float* __restrict__ y)
{
    int qt = blockIdx.x, h = blockIdx.y, b = blockIdx.z;
    int tid = threadIdx.x;
    int qg = qt * QT + tid;
    __shared__ float Ks[KT][HD];
    __shared__ float Vs[KT][HD];

    float q[HD], o[HD];
    const float* qp = qkv + ((size_t)(b * T + qg) * 3 * E) + h * HD;
    const float scale = 0.125f;
    #pragma unroll
    for (int d = 0; d < HD; d += 4) {
        float4 v = *(const float4*)(qp + d);
        q[d] = v.x * scale; q[d+1] = v.y * scale;
        q[d+2] = v.z * scale; q[d+3] = v.w * scale;
        o[d] = 0.f; o[d+1] = 0.f; o[d+2] = 0.f; o[d+3] = 0.f;
    }
    float m = -INFINITY, l = 0.f;
    int kend = qt * QT + QT;

    for (int k0 = 0; k0 < kend; k0 += KT) {
        __syncthreads();
        for (int i = tid; i < KT * HD / 4; i += 128) {
            int j = i >> 4;
            int c = (i & 15) << 2;
            const float* kp = qkv + ((size_t)(b * T + k0 + j) * 3 * E) + E + h * HD + c;
            *(float4*)&Ks[j][c] = *(const float4*)kp;
            *(float4*)&Vs[j][c] = *(const float4*)(kp + E);
        }
        __syncthreads();

        #pragma unroll 1
        for (int jc = 0; jc < KT; jc += KCH) {
            if (k0 + jc > qg) break;
            float s[KCH];
            float cm = -INFINITY;
            #pragma unroll
            for (int jj = 0; jj < KCH; jj++) {
                int kg = k0 + jc + jj;
                float acc = 0.f;
                #pragma unroll
                for (int d = 0; d < HD; d++) acc += q[d] * Ks[jc + jj][d];
                s[jj] = (kg <= qg) ? acc : -INFINITY;
                cm = fmaxf(cm, s[jj]);
            }
            float nm = fmaxf(m, cm);
            float corr = __expf(m - nm);
            l *= corr;
            #pragma unroll
            for (int d = 0; d < HD; d++) o[d] *= corr;
            #pragma unroll
            for (int jj = 0; jj < KCH; jj++) {
                float p = __expf(s[jj] - nm);
                l += p;
                #pragma unroll
                for (int d = 0; d < HD; d++) o[d] += p * Vs[jc + jj][d];
            }
            m = nm;
        }
    }
    float inv = 1.f / l;
    float* yp = y + ((size_t)(b * T + qg) * E) + h * HD;
    #pragma unroll
    for (int d = 0; d < HD; d += 4) {
        float4 v = make_float4(o[d] * inv, o[d+1] * inv, o[d+2] * inv, o[d+3] * inv);
        *(float4*)(yp + d) = v;
    }
}

// ---------------- loss ------------------------------------------------------
__global__ void loss_rows_kernel(const float* __restrict__ logits,
                                 const int* __restrict__ tgt)
{
    int row = blockIdx.x;
    int tid = threadIdx.x;
    const float* lr = logits + (size_t)row * V;
    __shared__ float red[32];

    float mx = -INFINITY;
    for (int i = tid; i < V; i += 256) mx = fmaxf(mx, lr[i]);
    #pragma unroll
    for (int o = 16; o > 0; o >>= 1)
        mx = fmaxf(mx, __shfl_xor_sync(0xffffffffu, mx, o));
    if ((tid & 31) == 0) red[tid >> 5] = mx;
    __syncthreads();
    if (tid < 32) {
        float v = (tid < 8) ? red[tid] : -INFINITY;
        #pragma unroll
        for (int o = 16; o > 0; o >>= 1)
            v = fmaxf(v, __shfl_xor_sync(0xffffffffu, v, o));
        if (tid == 0) red[0] = v;
    }
    __syncthreads();
    mx = red[0];
    __syncthreads();

    float sum = 0.f;
    for (int i = tid; i < V; i += 256) sum += __expf(lr[i] - mx);
    #pragma unroll
    for (int o = 16; o > 0; o >>= 1)
        sum += __shfl_xor_sync(0xffffffffu, sum, o);
    if ((tid & 31) == 0) red[tid >> 5] = sum;
    __syncthreads();
    if (tid == 0) {
        float tot = 0.f;
        for (int w = 0; w < 8; w++) tot += red[w];
        float lse = mx + logf(tot);
        int tg = tgt[row];
        g_nll[row] = (tg != -1) ? (lse - lr[tg]) : 0.f;
    }
}

__global__ void loss_final_kernel(const int* __restrict__ tgt,
                                  float* __restrict__ out_loss)
{
    int tid = threadIdx.x;
    float s = 0.f;
    int c = 0;
    for (int i = tid; i < BT; i += blockDim.x) {
        s += g_nll[i];
        if (tgt[i] != -1) c++;
    }
    __shared__ float sf[32];
    __shared__ int si[32];
    #pragma unroll
    for (int o = 16; o > 0; o >>= 1) {
        s += __shfl_xor_sync(0xffffffffu, s, o);
        c += __shfl_xor_sync(0xffffffffu, c, o);
    }
    if ((tid & 31) == 0) { sf[tid >> 5] = s; si[tid >> 5] = c; }
    __syncthreads();
    if (tid == 0) {
        int nw = blockDim.x >> 5;
        float ts = 0.f; int tc = 0;
        for (int w = 0; w < nw; w++) { ts += sf[w]; tc += si[w]; }
        out_loss[0] = ts / fmaxf((float)tc, 1.f);
    }
}

// ---------------- launch ----------------------------------------------------
extern "C" void kernel_launch(void* const* d_in, const int* in_sizes, int n_in,
                              void* d_out, int out_size)
{
    const int*   idx         = (const int*)d_in[0];
    const int*   targets     = (const int*)d_in[1];
    const float* wte         = (const float*)d_in[2];
    const float* wpe         = (const float*)d_in[3];
    const float* ln1_w       = (const float*)d_in[4];
    const float* ln1_b       = (const float*)d_in[5];
    const float* attn_w      = (const float*)d_in[6];
    const float* attn_proj_w = (const float*)d_in[7];
    const float* ln2_w       = (const float*)d_in[8];
    const float* ln2_b       = (const float*)d_in[9];
    const float* fc_w        = (const float*)d_in[10];
    const float* fc_proj_w   = (const float*)d_in[11];
    const float* lnf_w       = (const float*)d_in[12];
    const float* lnf_b       = (const float*)d_in[13];
    const float* lm_w        = (const float*)d_in[14];
    float* out = (float*)d_out;

    float *gx, *gh, *gqkv, *gy, *gmlp;
    cudaGetSymbolAddress((void**)&gx,   g_x);
    cudaGetSymbolAddress((void**)&gh,   g_h);
    cudaGetSymbolAddress((void**)&gqkv, g_qkv);
    cudaGetSymbolAddress((void**)&gy,   g_y);
    cudaGetSymbolAddress((void**)&gmlp, g_mlp);

    embed_kernel<<<BT, 256>>>(idx, wte, wpe, gx);

    for (int i = 0; i < NL; i++) {
        ln_kernel<<<BT, 256>>>(gx, ln1_w + (size_t)i * E, ln1_b + (size_t)i * E, gh);
        gemm_tf32<<<dim3((3 * E) / BN, BT / BM), 256>>>(
            gh, attn_w + (size_t)i * 3 * E * E, gqkv, nullptr, BT, 3 * E, E, 0);
        attn_kernel<<<dim3(T / QT, NH, B), 128>>>(gqkv, gy);
        gemm_tf32<<<dim3(E / BN, BT / BM), 256>>>(
            gy, attn_proj_w + (size_t)i * E * E, gx, gx, BT, E, E, 0);
        ln_kernel<<<BT, 256>>>(gx, ln2_w + (size_t)i * E, ln2_b + (size_t)i * E, gh);
        gemm_tf32<<<dim3((4 * E) / BN, BT / BM), 256>>>(
            gh, fc_w + (size_t)i * 4 * E * E, gmlp, nullptr, BT, 4 * E, E, 1);
        gemm_tf32<<<dim3(E / BN, BT / BM), 256>>>(
            gmlp, fc_proj_w + (size_t)i * E * 4 * E, gx, gx, BT, E, 4 * E, 0);
    }

    ln_kernel<<<BT, 256>>>(gx, lnf_w, lnf_b, gh);
    gemm_tf32<<<dim3((V + BN - 1) / BN, BT / BM), 256>>>(
        gh, lm_w, out, nullptr, BT, V, E, 0);

    long long btv = (long long)BT * V;
    if ((long long)out_size > btv) {
        loss_rows_kernel<<<BT, 256>>>(out, targets);
        loss_final_kernel<<<1, 1024>>>(targets, out + btv);
    }
}

// round 5
// speedup vs baseline: 3.9955x; 2.4678x over previous
#include <cuda_runtime.h>
#include <cuda_fp16.h>
#include <cstdint>
#include <math.h>

#define NL 6
#define NH 16
#define E  1024
#define V  50257
#define B  4
#define T  1024
#define BT (B*T)
#define HD 64

// ---------------- scratch ---------------------------------------------------
__device__ float  g_x[BT * E];             // residual stream (fp32)
__device__ float  g_qkv[BT * 3 * E];       // qkv (fp32, feeds attention)
__device__ float  g_nll[BT];
__device__ __half g_a16[BT * E];           // fp16 activations (LN out / attn out)
__device__ __half g_m16[BT * 4 * E];       // fp16 MLP hidden (GELU out)
// fp16 weights (converted once per launch)
__device__ __half g_w_qkv[NL * 3 * E * E];
__device__ __half g_w_proj[NL * E * E];
__device__ __half g_w_fc[NL * 4 * E * E];
__device__ __half g_w_fcp[NL * 4 * E * E];
__device__ __half g_w_lm[(size_t)V * E];

// ---------------- fp32 -> fp16 conversion -----------------------------------
__global__ void cvt_kernel(const float* __restrict__ s, __half* __restrict__ d, long n)
{
    long i = (long)blockIdx.x * blockDim.x + threadIdx.x;
    long stride = (long)gridDim.x * blockDim.x;
    for (long j = i * 4; j < n; j += stride * 4) {
        float4 v = *(const float4*)(s + j);
        *(__half2*)(d + j)     = __floats2half2_rn(v.x, v.y);
        *(__half2*)(d + j + 2) = __floats2half2_rn(v.z, v.w);
    }
}

// ---------------- embedding -------------------------------------------------
__global__ void embed_kernel(const int* __restrict__ idx,
                             const float* __restrict__ wte,
                             const float* __restrict__ wpe,
                             float* __restrict__ out)
{
    int row = blockIdx.x;
    int t = row % T;
    int tok = idx[row];
    const float* we = wte + (size_t)tok * E;
    const float* wp = wpe + (size_t)t * E;
    float* o = out + (size_t)row * E;
    for (int i = threadIdx.x; i < E; i += blockDim.x)
        o[i] = we[i] + wp[i];
}

// ---------------- layernorm (fp32 in, fp16 out) -----------------------------
__global__ void ln_kernel(const float* __restrict__ x,
                          const float* __restrict__ w,
                          const float* __restrict__ b,
                          __half* __restrict__ out)
{
    int row = blockIdx.x;
    int tid = threadIdx.x;
    const float* xr = x + (size_t)row * E;
    float s = 0.f, ss = 0.f;
    for (int i = tid; i < E; i += blockDim.x) {
        float v = xr[i];
        s += v; ss += v * v;
    }
    __shared__ float rs[32], rss[32];
    #pragma unroll
    for (int o = 16; o > 0; o >>= 1) {
        s  += __shfl_xor_sync(0xffffffffu, s, o);
        ss += __shfl_xor_sync(0xffffffffu, ss, o);
    }
    int wid = tid >> 5, lid = tid & 31;
    if (lid == 0) { rs[wid] = s; rss[wid] = ss; }
    __syncthreads();
    if (tid < 32) {
        int nw = blockDim.x >> 5;
        float a = (tid < nw) ? rs[tid] : 0.f;
        float c = (tid < nw) ? rss[tid] : 0.f;
        #pragma unroll
        for (int o = 16; o > 0; o >>= 1) {
            a += __shfl_xor_sync(0xffffffffu, a, o);
            c += __shfl_xor_sync(0xffffffffu, c, o);
        }
        if (tid == 0) { rs[0] = a; rss[0] = c; }
    }
    __syncthreads();
    float mu  = rs[0] * (1.0f / E);
    float var = rss[0] * (1.0f / E) - mu * mu;
    float r = rsqrtf(var + 1e-5f);
    __half* orow = out + (size_t)row * E;
    for (int i = tid; i < E; i += blockDim.x)
        orow[i] = __float2half((xr[i] - mu) * r * w[i] + b[i]);
}

// ---------------- fp16 tensor-core GEMM (legacy mma + ldmatrix + cp.async) --
// C[4096,N] = A[4096,K]h @ W[N,K]h^T (+Res fp32, optional exact GELU)
#define BM 128
#define BN 128
#define BKH 32
#define STG 4
#define ROWB 80                      // 64B data + 16B pad: LDSM conflict-free
#define STAGE_B (BM * ROWB)          // 10240 B
#define GSMEM (2 * STG * STAGE_B)    // 81920 B

#define LDSM4(r, a) \
    asm volatile("ldmatrix.sync.aligned.m8n8.x4.shared.b16 {%0,%1,%2,%3}, [%4];" \
        : "=r"((r)[0]), "=r"((r)[1]), "=r"((r)[2]), "=r"((r)[3]) : "r"(a))

#define MMA16816(c, a, b0, b1) \
    asm volatile("mma.sync.aligned.m16n8k16.row.col.f32.f16.f16.f32 " \
        "{%0,%1,%2,%3}, {%4,%5,%6,%7}, {%8,%9}, {%0,%1,%2,%3};" \
        : "+f"((c)[0]), "+f"((c)[1]), "+f"((c)[2]), "+f"((c)[3]) \
        : "r"((a)[0]), "r"((a)[1]), "r"((a)[2]), "r"((a)[3]), "r"(b0), "r"(b1))

__device__ __forceinline__ uint32_t smem_u32(const void* p) {
    uint32_t a;
    asm("{ .reg .u64 t; cvta.to.shared.u64 t, %1; cvt.u32.u64 %0, t; }" : "=r"(a) : "l"(p));
    return a;
}

__global__ void __launch_bounds__(256, 2)
gemm_h(const __half* __restrict__ A, const __half* __restrict__ Bw,
       float* __restrict__ Cf, __half* __restrict__ Ch,
       const float* __restrict__ Res, int N, int K, int act_gelu)
{
    extern __shared__ char sm[];
    uint32_t sA = smem_u32(sm);
    uint32_t sB = sA + STG * STAGE_B;

    int tid = threadIdx.x;
    int warp = tid >> 5, lane = tid & 31;
    int wm = warp & 3, wn = warp >> 2;
    int lrow = lane & 7, lsel = lane >> 3;
    int gq = lane >> 2, tg = lane & 3;
    int row0 = blockIdx.y * BM, col0 = blockIdx.x * BN;
    int ktiles = K / BKH;

    float acc[2][8][4];
    #pragma unroll
    for (int mi = 0; mi < 2; mi++)
        #pragma unroll
        for (int ni = 0; ni < 8; ni++)
            #pragma unroll
            for (int r = 0; r < 4; r++) acc[mi][ni][r] = 0.f;

#define ISSUE(st, kt) do { \
    size_t kofs = (size_t)(kt) * BKH; \
    _Pragma("unroll") \
    for (int ii = 0; ii < 2; ii++) { \
        int idx = tid + 256 * ii; int r = idx >> 2; int c = idx & 3; \
        uint32_t da = sA + (st) * STAGE_B + r * ROWB + c * 16; \
        const __half* ga = A + (size_t)(row0 + r) * K + kofs + c * 8; \
        asm volatile("cp.async.cg.shared.global [%0], [%1], 16;" :: "r"(da), "l"(ga)); \
        int brow = col0 + r; \
        int sz = (brow < N) ? 16 : 0; \
        const __half* gb = Bw + (size_t)(brow < N ? brow : 0) * K + kofs + c * 8; \
        uint32_t db = sB + (st) * STAGE_B + r * ROWB + c * 16; \
        asm volatile("cp.async.cg.shared.global [%0], [%1], 16, %2;" :: "r"(db), "l"(gb), "r"(sz)); \
    } \
} while (0)

    ISSUE(0, 0); asm volatile("cp.async.commit_group;" ::: "memory");
    ISSUE(1, 1); asm volatile("cp.async.commit_group;" ::: "memory");
    ISSUE(2, 2); asm volatile("cp.async.commit_group;" ::: "memory");

    for (int kt = 0; kt < ktiles; kt++) {
        asm volatile("cp.async.wait_group 2;" ::: "memory");
        __syncthreads();
        int nk = kt + STG - 1;
        if (nk < ktiles) ISSUE(nk & 3, nk);
        asm volatile("cp.async.commit_group;" ::: "memory");

        int buf = kt & 3;
        uint32_t aw = sA + buf * STAGE_B
                    + (wm * 32 + (lsel & 1) * 8 + lrow) * ROWB + (lsel >> 1) * 16;
        uint32_t bw = sB + buf * STAGE_B
                    + (wn * 64 + (lsel >> 1) * 8 + lrow) * ROWB + (lsel & 1) * 16;
        #pragma unroll
        for (int ks = 0; ks < 2; ks++) {
            uint32_t a0[4], a1[4];
            LDSM4(a0, aw + ks * 32);
            LDSM4(a1, aw + 16 * ROWB + ks * 32);
            #pragma unroll
            for (int nj = 0; nj < 4; nj++) {
                uint32_t b[4];
                LDSM4(b, bw + nj * 16 * ROWB + ks * 32);
                MMA16816(acc[0][nj * 2],     a0, b[0], b[1]);
                MMA16816(acc[0][nj * 2 + 1], a0, b[2], b[3]);
                MMA16816(acc[1][nj * 2],     a1, b[0], b[1]);
                MMA16816(acc[1][nj * 2 + 1], a1, b[2], b[3]);
            }
        }
    }

    // epilogue (alignment-safe for odd N, e.g. lm_head V=50257)
    #pragma unroll
    for (int mi = 0; mi < 2; mi++) {
        #pragma unroll
        for (int ni = 0; ni < 8; ni++) {
            int row = row0 + wm * 32 + mi * 16 + gq;
            int col = col0 + wn * 64 + ni * 8 + tg * 2;
            #pragma unroll
            for (int h = 0; h < 2; h++) {
                int rr = row + h * 8;
                float v0 = acc[mi][ni][h * 2], v1 = acc[mi][ni][h * 2 + 1];
                size_t off = (size_t)rr * N + col;
                bool ok0 = col < N, ok1 = col + 1 < N;
                if (Res) {
                    if (ok0) v0 += Res[off];
                    if (ok1) v1 += Res[off + 1];
                }
                if (act_gelu) {
                    v0 = 0.5f * v0 * (1.0f + erff(v0 * 0.70710678118654752f));
                    v1 = 0.5f * v1 * (1.0f + erff(v1 * 0.70710678118654752f));
                }
                if (Ch) {
                    if (ok1) *(__half2*)(Ch + off) = __floats2half2_rn(v0, v1);
                    else if (ok0) Ch[off] = __float2half(v0);
                } else {
                    if (ok1 && ((off & 1) == 0)) {
                        *(float2*)(Cf + off) = make_float2(v0, v1);
                    } else {
                        if (ok0) Cf[off] = v0;
                        if (ok1) Cf[off + 1] = v1;
                    }
                }
            }
        }
    }
}

// ---------------- flash attention (fp32, causal, hd=64) ---------------------
#define QT 128
#define KT 64
#define KCH 16

__global__ void __launch_bounds__(128)
attn_kernel(const float* __restrict__ qkv, __half* __restrict__ y)
{
    int qt = blockIdx.x, h = blockIdx.y, b = blockIdx.z;
    int tid = threadIdx.x;
    int qg = qt * QT + tid;
    __shared__ float Ks[KT][HD];
    __shared__ float Vs[KT][HD];

    float q[HD], o[HD];
    const float* qp = qkv + ((size_t)(b * T + qg) * 3 * E) + h * HD;
    const float scale = 0.125f;
    #pragma unroll
    for (int d = 0; d < HD; d += 4) {
        float4 v = *(const float4*)(qp + d);
        q[d] = v.x * scale; q[d+1] = v.y * scale;
        q[d+2] = v.z * scale; q[d+3] = v.w * scale;
        o[d] = 0.f; o[d+1] = 0.f; o[d+2] = 0.f; o[d+3] = 0.f;
    }
    float m = -INFINITY, l = 0.f;
    int kend = qt * QT + QT;

    for (int k0 = 0; k0 < kend; k0 += KT) {
        __syncthreads();
        for (int i = tid; i < KT * HD / 4; i += 128) {
            int j = i >> 4;
            int c = (i & 15) << 2;
            const float* kp = qkv + ((size_t)(b * T + k0 + j) * 3 * E) + E + h * HD + c;
            *(float4*)&Ks[j][c] = *(const float4*)kp;
            *(float4*)&Vs[j][c] = *(const float4*)(kp + E);
        }
        __syncthreads();

        #pragma unroll 1
        for (int jc = 0; jc < KT; jc += KCH) {
            if (k0 + jc > qg) break;
            float s[KCH];
            float cm = -INFINITY;
            #pragma unroll
            for (int jj = 0; jj < KCH; jj++) {
                int kg = k0 + jc + jj;
                float acc = 0.f;
                #pragma unroll
                for (int d = 0; d < HD; d++) acc += q[d] * Ks[jc + jj][d];
                s[jj] = (kg <= qg) ? acc : -INFINITY;
                cm = fmaxf(cm, s[jj]);
            }
            float nm = fmaxf(m, cm);
            float corr = __expf(m - nm);
            l *= corr;
            #pragma unroll
            for (int d = 0; d < HD; d++) o[d] *= corr;
            #pragma unroll
            for (int jj = 0; jj < KCH; jj++) {
                float p = __expf(s[jj] - nm);
                l += p;
                #pragma unroll
                for (int d = 0; d < HD; d++) o[d] += p * Vs[jc + jj][d];
            }
            m = nm;
        }
    }
    float inv = 1.f / l;
    __half* yp = y + ((size_t)(b * T + qg) * E) + h * HD;
    #pragma unroll
    for (int d = 0; d < HD; d += 2)
        *(__half2*)(yp + d) = __floats2half2_rn(o[d] * inv, o[d+1] * inv);
}

// ---------------- loss ------------------------------------------------------
__global__ void loss_rows_kernel(const float* __restrict__ logits,
                                 const int* __restrict__ tgt)
{
    int row = blockIdx.x;
    int tid = threadIdx.x;
    const float* lr = logits + (size_t)row * V;
    __shared__ float red[32];

    float mx = -INFINITY;
    for (int i = tid; i < V; i += 256) mx = fmaxf(mx, lr[i]);
    #pragma unroll
    for (int o = 16; o > 0; o >>= 1)
        mx = fmaxf(mx, __shfl_xor_sync(0xffffffffu, mx, o));
    if ((tid & 31) == 0) red[tid >> 5] = mx;
    __syncthreads();
    if (tid < 32) {
        float v = (tid < 8) ? red[tid] : -INFINITY;
        #pragma unroll
        for (int o = 16; o > 0; o >>= 1)
            v = fmaxf(v, __shfl_xor_sync(0xffffffffu, v, o));
        if (tid == 0) red[0] = v;
    }
    __syncthreads();
    mx = red[0];
    __syncthreads();

    float sum = 0.f;
    for (int i = tid; i < V; i += 256) sum += __expf(lr[i] - mx);
    #pragma unroll
    for (int o = 16; o > 0; o >>= 1)
        sum += __shfl_xor_sync(0xffffffffu, sum, o);
    if ((tid & 31) == 0) red[tid >> 5] = sum;
    __syncthreads();
    if (tid == 0) {
        float tot = 0.f;
        for (int w = 0; w < 8; w++) tot += red[w];
        float lse = mx + logf(tot);
        int tg = tgt[row];
        g_nll[row] = (tg != -1) ? (lse - lr[tg]) : 0.f;
    }
}

__global__ void loss_final_kernel(const int* __restrict__ tgt,
                                  float* __restrict__ out_loss)
{
    int tid = threadIdx.x;
    float s = 0.f;
    int c = 0;
    for (int i = tid; i < BT; i += blockDim.x) {
        s += g_nll[i];
        if (tgt[i] != -1) c++;
    }
    __shared__ float sf[32];
    __shared__ int si[32];
    #pragma unroll
    for (int o = 16; o > 0; o >>= 1) {
        s += __shfl_xor_sync(0xffffffffu, s, o);
        c += __shfl_xor_sync(0xffffffffu, c, o);
    }
    if ((tid & 31) == 0) { sf[tid >> 5] = s; si[tid >> 5] = c; }
    __syncthreads();
    if (tid == 0) {
        int nw = blockDim.x >> 5;
        float ts = 0.f; int tc = 0;
        for (int w = 0; w < nw; w++) { ts += sf[w]; tc += si[w]; }
        out_loss[0] = ts / fmaxf((float)tc, 1.f);
    }
}

// ---------------- launch ----------------------------------------------------
extern "C" void kernel_launch(void* const* d_in, const int* in_sizes, int n_in,
                              void* d_out, int out_size)
{
    const int*   idx         = (const int*)d_in[0];
    const int*   targets     = (const int*)d_in[1];
    const float* wte         = (const float*)d_in[2];
    const float* wpe         = (const float*)d_in[3];
    const float* ln1_w       = (const float*)d_in[4];
    const float* ln1_b       = (const float*)d_in[5];
    const float* attn_w      = (const float*)d_in[6];
    const float* attn_proj_w = (const float*)d_in[7];
    const float* ln2_w       = (const float*)d_in[8];
    const float* ln2_b       = (const float*)d_in[9];
    const float* fc_w        = (const float*)d_in[10];
    const float* fc_proj_w   = (const float*)d_in[11];
    const float* lnf_w       = (const float*)d_in[12];
    const float* lnf_b       = (const float*)d_in[13];
    const float* lm_w        = (const float*)d_in[14];
    float* out = (float*)d_out;

    cudaFuncSetAttribute(gemm_h, cudaFuncAttributeMaxDynamicSharedMemorySize, GSMEM);

    float *gx, *gqkv;
    __half *ga16, *gm16, *wqkv, *wproj, *wfc, *wfcp, *wlm;
    cudaGetSymbolAddress((void**)&gx,    g_x);
    cudaGetSymbolAddress((void**)&gqkv,  g_qkv);
    cudaGetSymbolAddress((void**)&ga16,  g_a16);
    cudaGetSymbolAddress((void**)&gm16,  g_m16);
    cudaGetSymbolAddress((void**)&wqkv,  g_w_qkv);
    cudaGetSymbolAddress((void**)&wproj, g_w_proj);
    cudaGetSymbolAddress((void**)&wfc,   g_w_fc);
    cudaGetSymbolAddress((void**)&wfcp,  g_w_fcp);
    cudaGetSymbolAddress((void**)&wlm,   g_w_lm);

    // one-time weight conversions
    cvt_kernel<<<1024, 256>>>(attn_w,      wqkv,  (long)NL * 3 * E * E);
    cvt_kernel<<<1024, 256>>>(attn_proj_w, wproj, (long)NL * E * E);
    cvt_kernel<<<1024, 256>>>(fc_w,        wfc,   (long)NL * 4 * E * E);
    cvt_kernel<<<1024, 256>>>(fc_proj_w,   wfcp,  (long)NL * 4 * E * E);
    cvt_kernel<<<1024, 256>>>(lm_w,        wlm,   (long)V * E);

    embed_kernel<<<BT, 256>>>(idx, wte, wpe, gx);

    for (int i = 0; i < NL; i++) {
        ln_kernel<<<BT, 256>>>(gx, ln1_w + (size_t)i * E, ln1_b + (size_t)i * E, ga16);
        gemm_h<<<dim3(3 * E / BN, BT / BM), 256, GSMEM>>>(
            ga16, wqkv + (size_t)i * 3 * E * E, gqkv, nullptr, nullptr, 3 * E, E, 0);
        attn_kernel<<<dim3(T / QT, NH, B), 128>>>(gqkv, ga16);
        gemm_h<<<dim3(E / BN, BT / BM), 256, GSMEM>>>(
            ga16, wproj + (size_t)i * E * E, gx, nullptr, gx, E, E, 0);
        ln_kernel<<<BT, 256>>>(gx, ln2_w + (size_t)i * E, ln2_b + (size_t)i * E, ga16);
        gemm_h<<<dim3(4 * E / BN, BT / BM), 256, GSMEM>>>(
            ga16, wfc + (size_t)i * 4 * E * E, nullptr, gm16, nullptr, 4 * E, E, 1);
        gemm_h<<<dim3(E / BN, BT / BM), 256, GSMEM>>>(
            gm16, wfcp + (size_t)i * 4 * E * E, gx, nullptr, gx, E, 4 * E, 0);
    }

    ln_kernel<<<BT, 256>>>(gx, lnf_w, lnf_b, ga16);
    gemm_h<<<dim3((V + BN - 1) / BN, BT / BM), 256, GSMEM>>>(
        ga16, wlm, out, nullptr, nullptr, V, E, 0);

    long long btv = (long long)BT * V;
    if ((long long)out_size > btv) {
        loss_rows_kernel<<<BT, 256>>>(out, targets);
        loss_final_kernel<<<1, 1024>>>(targets, out + btv);
    }
}